// round 10
// baseline (speedup 1.0000x reference)
#include <cuda_runtime.h>
#include <cstdint>

#define Bv 4
#define Nv 512
#define Dv 256
#define Lv 64

typedef unsigned long long ull;

// Projected+weighted features, layout [b][l][n]  (512 KB)
__device__ float g_xh[Bv * Lv * Nv];
// Device-wide barrier (replay-safe: count resets, release monotone)
__device__ unsigned g_count = 0;
__device__ unsigned g_release = 0;
// Pair handshake: per-CTA row sums + monotone flags
__device__ float    g_psum[256 * 16];
__device__ unsigned g_pflag[256];

__device__ __forceinline__ ull pk2(float a) {
    ull r;
    asm("mov.b64 %0, {%1, %2};" : "=l"(r) : "f"(a), "f"(a));
    return r;
}
__device__ __forceinline__ ull add2(ull a, ull b) {
    ull r;
    asm("add.rn.f32x2 %0, %1, %2;" : "=l"(r) : "l"(a), "l"(b));
    return r;
}
__device__ __forceinline__ float lo2(ull a) {
    float x, y;
    asm("mov.b64 {%0, %1}, %2;" : "=f"(x), "=f"(y) : "l"(a));
    return x;
}
__device__ __forceinline__ float hi2(ull a) {
    float x, y;
    asm("mov.b64 {%0, %1}, %2;" : "=f"(x), "=f"(y) : "l"(a));
    return y;
}

// ---------------------------------------------------------------------------
// Grid 256 = (tile = b*32 + it) * 2 + jh.  512 threads, ~91 KB smem,
// 2 CTAs/SM.  Each CTA: 16 i-rows x 256 j (its half) x full l=64.
// Smem floats: sjh[0,16384) | si2[16384,18432) | adjs[18432,22528)
//              | red[22528,22592) ; phase-A overlay Wt@0, xs@18432 (+4352)
// ---------------------------------------------------------------------------
__global__ __launch_bounds__(512, 2) void fused_kernel(
    const float* __restrict__ x, const float* __restrict__ adj,
    const float* __restrict__ W, const float* __restrict__ lw,
    float* __restrict__ out) {
    extern __shared__ float sm[];
    float* sjh  = sm;                       // [64][256]
    ull*   si2  = (ull*)(sm + 16384);       // [64][16] {-wv,-wv}
    float* adjs = sm + 18432;               // [16][256]
    float* red  = sm + 22528;               // [16][4]
    float* Wt = sm;                         // [256][68] (phase A)
    float* xs = sm + 18432;                 // [256][17] (phase A)

    int cta  = blockIdx.x;
    int tile = cta >> 1;
    int jh   = cta & 1;
    int b    = tile >> 5;
    int i0   = (tile & 31) << 4;
    int tid  = threadIdx.x;

    // ---------------- Phase A: jh==0 CTA projects its 16 i-rows ------------
    if (jh == 0) {
        for (int idx = tid; idx < 16 * 256; idx += 512) {
            int rr = idx >> 8, d = idx & 255;
            xs[d * 17 + rr] = x[(b * Nv + i0 + rr) * Dv + d];
        }
        for (int idx = tid; idx < 64 * 256; idx += 512) {
            int l = idx >> 8, d = idx & 255;
            Wt[d * 68 + l] = W[l * Dv + d];
        }
        __syncthreads();
        if (tid < 256) {
            int r  = tid & 15;
            int l0 = (tid >> 4) << 2;
            float a0 = 0.f, a1 = 0.f, a2 = 0.f, a3 = 0.f;
#pragma unroll 8
            for (int d = 0; d < 256; ++d) {
                float  xv = xs[d * 17 + r];
                float4 wq = *(const float4*)&Wt[d * 68 + l0];
                a0 = fmaf(xv, wq.x, a0);
                a1 = fmaf(xv, wq.y, a1);
                a2 = fmaf(xv, wq.z, a2);
                a3 = fmaf(xv, wq.w, a3);
            }
            a0 *= lw[l0 + 0];
            a1 *= lw[l0 + 1];
            a2 *= lw[l0 + 2];
            a3 *= lw[l0 + 3];
            float* dst = g_xh + b * (Lv * Nv) + i0 + r;
            dst[(l0 + 0) * Nv] = a0;
            dst[(l0 + 1) * Nv] = a1;
            dst[(l0 + 2) * Nv] = a2;
            dst[(l0 + 3) * Nv] = a3;
        }
        __syncthreads();
    }

    // ---------------- Device-wide barrier (256 arrivals) --------------------
    if (tid == 0) {
        __threadfence();
        unsigned snap = *(volatile unsigned*)&g_release;
        unsigned old  = atomicAdd(&g_count, 1);
        if (old == gridDim.x - 1) {
            g_count = 0;
            __threadfence();
            atomicAdd(&g_release, 1);
        } else {
            while (*(volatile unsigned*)&g_release == snap) __nanosleep(32);
        }
        __threadfence();
    }
    __syncthreads();

    // ---------------- Phase B staging ---------------------------------------
    const float* xh = g_xh + b * (Lv * Nv);
    // si2: 1024 entries, packed negated i-row values
    for (int idx = tid; idx < 1024; idx += 512) {
        int l = idx >> 4, r = idx & 15;
        si2[idx] = pk2(-xh[l * Nv + i0 + r]);
    }
    // sjh: this CTA's j-half of all 64 l rows
    for (int idx = tid; idx < 4096; idx += 512) {
        int l = idx >> 6, c4 = idx & 63;
        ((float4*)sjh)[idx] = *(const float4*)&xh[l * Nv + jh * 256 + c4 * 4];
    }
    // adjs: 16 x 256 tile
    for (int idx = tid; idx < 1024; idx += 512) {
        int r = idx >> 6, c4 = idx & 63;
        ((float4*)adjs)[idx] =
            *(const float4*)&adj[(size_t)(b * Nv + i0 + r) * Nv + jh * 256 + c4 * 4];
    }
    __syncthreads();

    // ---------------- Mainloop ----------------------------------------------
    int w    = tid >> 5;
    int lane = tid & 31;
    int rg   = w & 3;          // rows 4rg..4rg+3
    int jq   = w >> 2;         // j chunk of 64
    int jloc = jq * 64 + lane * 2;

    const ull ABS2 = 0x7FFFFFFF7FFFFFFFull;
    ull acc0 = 0, acc1 = 0, acc2 = 0, acc3 = 0;

    const float* sjp = sjh + jloc;
    const ull*   sip = si2 + rg * 4;

#pragma unroll 8
    for (int l = 0; l < 64; ++l) {
        ull j2 = *(const ull*)(sjp + l * 256);
        ulonglong2 nab = *(const ulonglong2*)(sip + l * 16);
        ulonglong2 ncd = *(const ulonglong2*)(sip + l * 16 + 2);
        acc0 = add2(acc0, add2(j2, nab.x) & ABS2);
        acc1 = add2(acc1, add2(j2, nab.y) & ABS2);
        acc2 = add2(acc2, add2(j2, ncd.x) & ABS2);
        acc3 = add2(acc3, add2(j2, ncd.y) & ABS2);
    }

    // ---------------- Epilogue: leaky + adj*exp (no max: e^d bounded) ------
    float e0[4], e1[4];
    {
        ull accs[4] = {acc0, acc1, acc2, acc3};
#pragma unroll
        for (int r = 0; r < 4; ++r) {
            int row = rg * 4 + r;
            float dl = lo2(accs[r]);
            float dh = hi2(accs[r]);
            dl = dl > 0.f ? dl : 0.01f * dl;
            dh = dh > 0.f ? dh : 0.01f * dh;
            float2 a2v = *(const float2*)&adjs[row * 256 + jloc];
            float el = a2v.x * __expf(dl);
            float eh = a2v.y * __expf(dh);
            e0[r] = el; e1[r] = eh;
            float sr = el + eh;
#pragma unroll
            for (int o = 16; o; o >>= 1)
                sr += __shfl_xor_sync(0xffffffffu, sr, o);
            if (lane == 0) red[row * 4 + jq] = sr;
        }
    }
    __syncthreads();

    // ---------------- Cross-half sum exchange (pair handshake) --------------
    if (tid < 16) {
        float S = red[tid * 4 + 0] + red[tid * 4 + 1] +
                  red[tid * 4 + 2] + red[tid * 4 + 3];
        *(volatile float*)&g_psum[cta * 16 + tid] = S;
        __threadfence();
    }
    __syncthreads();
    if (tid == 0) {
        unsigned my = atomicAdd(&g_pflag[cta], 1) + 1;
        while (*(volatile unsigned*)&g_pflag[cta ^ 1] < my) __nanosleep(32);
        __threadfence();
    }
    __syncthreads();

    // ---------------- Normalize + store -------------------------------------
#pragma unroll
    for (int r = 0; r < 4; ++r) {
        int row = rg * 4 + r;
        float Sl = red[row * 4 + 0] + red[row * 4 + 1] +
                   red[row * 4 + 2] + red[row * 4 + 3];
        float Sp = __ldcg(&g_psum[(cta ^ 1) * 16 + row]);
        float rs = 1.0f / (Sl + Sp);
        float2 o2;
        o2.x = e0[r] * rs + 1e-10f;
        o2.y = e1[r] * rs + 1e-10f;
        *(float2*)&out[(size_t)(b * Nv + i0 + row) * Nv + jh * 256 + jloc] = o2;
    }
}

extern "C" void kernel_launch(void* const* d_in, const int* in_sizes, int n_in,
                              void* d_out, int out_size) {
    (void)in_sizes; (void)n_in; (void)out_size;
    const float* x   = (const float*)d_in[0];
    const float* adj = (const float*)d_in[1];
    const float* W   = (const float*)d_in[2];
    const float* lw  = (const float*)d_in[3];
    float* out = (float*)d_out;

    const int smem = 22784 * 4;   // 91136 B per CTA -> 2 CTAs/SM
    cudaFuncSetAttribute(fused_kernel,
                         cudaFuncAttributeMaxDynamicSharedMemorySize, smem);
    cudaFuncSetAttribute(fused_kernel,
                         cudaFuncAttributePreferredSharedMemoryCarveout,
                         cudaSharedmemCarveoutMaxShared);

    fused_kernel<<<2 * Bv * (Nv / 16), 512, smem>>>(x, adj, W, lw, out);
}